// round 9
// baseline (speedup 1.0000x reference)
#include <cuda_runtime.h>
#include <cuda_bf16.h>

// ---------------------------------------------------------------------------
// GATv2 x2 on GB300.
//   CSR build (hist + scan + scatter), GEMM1 packed-f32x2, warp-per-node
//   online segment softmax aggregations, GEMM2, fused log_softmax.
// ---------------------------------------------------------------------------

#define NMAX 100000
#define EMAX 1700000
#define IN_DIM 256
#define C1 64            // heads*hid layer 1
#define C2 40            // out dim layer 2
#define NEG_SLOPE 0.2f

// scratch (device globals; no allocation allowed)
__device__ float g_xl1[NMAX * C1];
__device__ float g_xr1[NMAX * C1];
__device__ float g_h  [NMAX * C1];
__device__ float g_xl2[NMAX * C2];
__device__ float g_xr2[NMAX * C2];
__device__ int   g_deg[NMAX];
__device__ int   g_cursor[NMAX];
__device__ int   g_rowptr[NMAX + 1];
__device__ int   g_col[EMAX];
__device__ int   g_bsums[256];   // NB = ceil(100000/1024) = 98 < 128: safe

// packed fp32x2 FMA (Blackwell FFMA2 — only reachable via PTX)
__device__ __forceinline__ unsigned long long ffma2(
    unsigned long long a, unsigned long long b, unsigned long long c)
{
    unsigned long long d;
    asm("fma.rn.f32x2 %0, %1, %2, %3;" : "=l"(d) : "l"(a), "l"(b), "l"(c));
    return d;
}
__device__ __forceinline__ float2 unpack2(unsigned long long v) {
    float2 f;
    asm("mov.b64 {%0, %1}, %2;" : "=f"(f.x), "=f"(f.y) : "l"(v));
    return f;
}

// ---------------------------------------------------------------------------
// K0: zero deg + cursor
__global__ void k_zero(int n) {
    int i = blockIdx.x * blockDim.x + threadIdx.x;
    if (i < n) { g_deg[i] = 0; g_cursor[i] = 0; }
}

// K1: degree histogram over dst
__global__ void k_hist(const int* __restrict__ dst, int E) {
    int e = blockIdx.x * blockDim.x + threadIdx.x;
    if (e < E) atomicAdd(&g_deg[dst[e]], 1);
}

// K2a: per-block exclusive scan (1024 elems / block)
__global__ void k_scan_block(int n) {
    __shared__ int warpSums[32];
    int t = threadIdx.x;
    int i = blockIdx.x * 1024 + t;
    int v = (i < n) ? g_deg[i] : 0;
    int x = v;
    #pragma unroll
    for (int d = 1; d < 32; d <<= 1) {
        int y = __shfl_up_sync(0xffffffffu, x, d);
        if ((t & 31) >= d) x += y;
    }
    if ((t & 31) == 31) warpSums[t >> 5] = x;
    __syncthreads();
    if (t < 32) {
        int w = warpSums[t];
        #pragma unroll
        for (int d = 1; d < 32; d <<= 1) {
            int y = __shfl_up_sync(0xffffffffu, w, d);
            if (t >= d) w += y;
        }
        warpSums[t] = w;   // inclusive warp sums
    }
    __syncthreads();
    int warpOff = (t >= 32) ? warpSums[(t >> 5) - 1] : 0;
    int inc = x + warpOff;
    if (i < n) g_rowptr[i] = inc - v;       // exclusive within block
    if (t == 1023) g_bsums[blockIdx.x] = inc;
}

// K2b: parallel scan of block sums (nb <= 128), one block of 128 threads
__global__ void k_scan_sums(int nb) {
    __shared__ int ws[4];
    int t = threadIdx.x;                    // 0..127
    int v = (t < nb) ? g_bsums[t] : 0;
    int x = v;
    #pragma unroll
    for (int d = 1; d < 32; d <<= 1) {
        int y = __shfl_up_sync(0xffffffffu, x, d);
        if ((t & 31) >= d) x += y;
    }
    if ((t & 31) == 31) ws[t >> 5] = x;
    __syncthreads();
    int off = 0;
    #pragma unroll
    for (int w = 0; w < 4; ++w) if (w < (t >> 5)) off += ws[w];
    int inc = x + off;
    if (t <= nb) g_bsums[t] = inc - v;      // exclusive; t==nb gets total
}

// K2c: add block offsets; write rowptr[n]
__global__ void k_scan_add(int n, int nb) {
    int i = blockIdx.x * blockDim.x + threadIdx.x;
    if (i < n) g_rowptr[i] += g_bsums[i >> 10];
    if (i == 0) g_rowptr[n] = g_bsums[nb];
}

// K3: scatter src ids into CSR slots
__global__ void k_scatter(const int* __restrict__ src, const int* __restrict__ dst, int E) {
    int e = blockIdx.x * blockDim.x + threadIdx.x;
    if (e < E) {
        int d = dst[e];
        int pos = g_rowptr[d] + atomicAdd(&g_cursor[d], 1);
        g_col[pos] = src[e];
    }
}

// ---------------------------------------------------------------------------
// K4: GEMM1 with packed f32x2 FMA.
// Block 256 threads, tile 128 rows x 64 cols, both W matrices.
// Thread: 8 rows (4 packed row-pairs) x 4 cols per matrix.
// B tiles stored DUPLICATED in smem ((b,b) pairs) so the inner loop has zero
// packing instructions: 6x LDS.128 + 32x FFMA2 per k-step.
// NOTE: __align__(16) is load-bearing — the inner loop does 16B vector LDS.
__global__ void __launch_bounds__(256) k_gemm1(
    const float* __restrict__ x,
    const float* __restrict__ Wl, const float* __restrict__ bl,
    const float* __restrict__ Wr, const float* __restrict__ br,
    int n)
{
    __shared__ __align__(16) float As [16][128];
    __shared__ __align__(16) float Bdl[16][128];   // Bdl[k][2c]=Bdl[k][2c+1]=Wl[k][c]
    __shared__ __align__(16) float Bdr[16][128];
    const int t = threadIdx.x;
    const int row0 = blockIdx.x * 128;
    const int tr = t >> 4;          // 0..15 -> rows tr*8..+7
    const int tc = t & 15;          // 0..15 -> cols tc*4..+3

    const int m    = t & 127;       // A-load row
    const int half = t >> 7;        // 0/1 -> k-subrange
    const int r_load = row0 + m;
    const bool rok = (r_load < n);

    const int kb = t >> 4;          // B-load row within chunk
    const int cb = (t & 15) * 4;    // B-load col

    unsigned long long accL[4][4], accR[4][4];
    #pragma unroll
    for (int i = 0; i < 4; ++i)
        #pragma unroll
        for (int j = 0; j < 4; ++j) { accL[i][j] = 0ull; accR[i][j] = 0ull; }

    for (int k0 = 0; k0 < IN_DIM; k0 += 16) {
        // A: 128x16, transposed in smem
        float4 v0, v1;
        if (rok) {
            const float4* xp = (const float4*)(x + (size_t)r_load * IN_DIM + k0 + half * 8);
            v0 = xp[0]; v1 = xp[1];
        } else {
            v0 = make_float4(0.f,0.f,0.f,0.f); v1 = v0;
        }
        int kk = half * 8;
        As[kk+0][m] = v0.x; As[kk+1][m] = v0.y; As[kk+2][m] = v0.z; As[kk+3][m] = v0.w;
        As[kk+4][m] = v1.x; As[kk+5][m] = v1.y; As[kk+6][m] = v1.z; As[kk+7][m] = v1.w;
        // B tiles, duplicated
        float4 wl = *(const float4*)&Wl[(size_t)(k0 + kb) * C1 + cb];
        float4 wr = *(const float4*)&Wr[(size_t)(k0 + kb) * C1 + cb];
        *(float4*)&Bdl[kb][2*cb    ] = make_float4(wl.x, wl.x, wl.y, wl.y);
        *(float4*)&Bdl[kb][2*cb + 4] = make_float4(wl.z, wl.z, wl.w, wl.w);
        *(float4*)&Bdr[kb][2*cb    ] = make_float4(wr.x, wr.x, wr.y, wr.y);
        *(float4*)&Bdr[kb][2*cb + 4] = make_float4(wr.z, wr.z, wr.w, wr.w);
        __syncthreads();

        #pragma unroll
        for (int k = 0; k < 16; ++k) {
            const ulonglong2* apv = (const ulonglong2*)&As[k][tr * 8];
            ulonglong2 a01 = apv[0], a23 = apv[1];
            unsigned long long ap[4] = { a01.x, a01.y, a23.x, a23.y };
            const ulonglong2* blv = (const ulonglong2*)&Bdl[k][tc * 8];
            ulonglong2 bl0 = blv[0], bl1 = blv[1];
            unsigned long long bld[4] = { bl0.x, bl0.y, bl1.x, bl1.y };
            const ulonglong2* brv = (const ulonglong2*)&Bdr[k][tc * 8];
            ulonglong2 br0 = brv[0], br1 = brv[1];
            unsigned long long brd[4] = { br0.x, br0.y, br1.x, br1.y };
            #pragma unroll
            for (int i = 0; i < 4; ++i)
                #pragma unroll
                for (int j = 0; j < 4; ++j) {
                    accL[i][j] = ffma2(ap[i], bld[j], accL[i][j]);
                    accR[i][j] = ffma2(ap[i], brd[j], accR[i][j]);
                }
        }
        __syncthreads();
    }

    // epilogue: accL[i][j] = (row tr*8+2i, row tr*8+2i+1) at col tc*4+j
    float4 bly = *(const float4*)&bl[tc * 4];
    float4 bry = *(const float4*)&br[tc * 4];
    #pragma unroll
    for (int i = 0; i < 4; ++i) {
        float2 l0 = unpack2(accL[i][0]), l1 = unpack2(accL[i][1]);
        float2 l2 = unpack2(accL[i][2]), l3 = unpack2(accL[i][3]);
        float2 r0 = unpack2(accR[i][0]), r1 = unpack2(accR[i][1]);
        float2 r2 = unpack2(accR[i][2]), r3 = unpack2(accR[i][3]);
        int rEven = row0 + tr * 8 + 2 * i;
        if (rEven < n) {
            *(float4*)&g_xl1[(size_t)rEven * C1 + tc * 4] =
                make_float4(l0.x+bly.x, l1.x+bly.y, l2.x+bly.z, l3.x+bly.w);
            *(float4*)&g_xr1[(size_t)rEven * C1 + tc * 4] =
                make_float4(r0.x+bry.x, r1.x+bry.y, r2.x+bry.z, r3.x+bry.w);
        }
        if (rEven + 1 < n) {
            *(float4*)&g_xl1[(size_t)(rEven+1) * C1 + tc * 4] =
                make_float4(l0.y+bly.x, l1.y+bly.y, l2.y+bly.z, l3.y+bly.w);
            *(float4*)&g_xr1[(size_t)(rEven+1) * C1 + tc * 4] =
                make_float4(r0.y+bry.x, r1.y+bry.y, r2.y+bry.z, r3.y+bry.w);
        }
    }
}

// ---------------------------------------------------------------------------
// K5: layer-1 aggregation. One warp per node, online segment softmax.
__global__ void __launch_bounds__(256) k_agg1(
    const float* __restrict__ att, const float* __restrict__ bias, int n)
{
    int wid = (blockIdx.x * blockDim.x + threadIdx.x) >> 5;
    int lane = threadIdx.x & 31;
    if (wid >= n) return;
    const int c0 = lane * 2;
    float2 xrv = *(const float2*)(g_xr1 + (size_t)wid * C1 + c0);
    float a0 = att[c0], a1 = att[c0 + 1];

    float mx = -1e30f, s = 0.f, acc0 = 0.f, acc1 = 0.f;
    int beg = g_rowptr[wid];
    int cnt = g_rowptr[wid + 1] - beg;

    for (int it = -1; it < cnt; ++it) {
        int src = (it < 0) ? wid : g_col[beg + it];
        float2 lv = *(const float2*)(g_xl1 + (size_t)src * C1 + c0);
        float m0 = lv.x + xrv.x, m1 = lv.y + xrv.y;
        float h0 = m0 > 0.f ? m0 : NEG_SLOPE * m0;
        float h1 = m1 > 0.f ? m1 : NEG_SLOPE * m1;
        float p = h0 * a0 + h1 * a1;
        p += __shfl_xor_sync(0xffffffffu, p, 1);
        p += __shfl_xor_sync(0xffffffffu, p, 2);   // head logit in all 4 lanes
        if (p > mx) {
            float f = __expf(mx - p);
            s *= f; acc0 *= f; acc1 *= f; mx = p;
        }
        float w = __expf(p - mx);
        s += w;
        acc0 += w * lv.x;
        acc1 += w * lv.y;
    }
    float o0 = acc0 / s + bias[c0];
    float o1 = acc1 / s + bias[c0 + 1];
    o0 = o0 > 0.f ? o0 : (__expf(o0) - 1.f);   // ELU
    o1 = o1 > 0.f ? o1 : (__expf(o1) - 1.f);
    *(float2*)(g_h + (size_t)wid * C1 + c0) = make_float2(o0, o1);
}

// ---------------------------------------------------------------------------
// K6: GEMM2. Block: 256 threads, tile 64 rows x 40 cols, K=64, both W's.
__global__ void __launch_bounds__(256) k_gemm2(
    const float* __restrict__ Wl, const float* __restrict__ bl,
    const float* __restrict__ Wr, const float* __restrict__ br,
    int n)
{
    __shared__ float hs[64][65];
    __shared__ float Bls[64 * C2];
    __shared__ float Brs[64 * C2];
    const int t = threadIdx.x;
    const int row0 = blockIdx.x * 64;

    for (int i = t; i < 64 * C2; i += 256) { Bls[i] = Wl[i]; Brs[i] = Wr[i]; }
    #pragma unroll
    for (int j = 0; j < 16; ++j) {
        int linear = j * 256 + t;
        int m = linear >> 6, k = linear & 63;
        int r = row0 + m;
        hs[m][k] = (r < n) ? g_h[(size_t)r * C1 + k] : 0.f;
    }
    __syncthreads();

    const int tr = t >> 3;          // 0..31 -> rows tr*2, tr*2+1
    const int tc = (t & 7) * 5;     // cols tc..tc+4
    float accL[2][5] = {{0}}; float accR[2][5] = {{0}};

    #pragma unroll 8
    for (int k = 0; k < 64; ++k) {
        float a0 = hs[tr * 2][k];
        float a1 = hs[tr * 2 + 1][k];
        #pragma unroll
        for (int j = 0; j < 5; ++j) {
            float wl = Bls[k * C2 + tc + j];
            float wr = Brs[k * C2 + tc + j];
            accL[0][j] += a0 * wl; accL[1][j] += a1 * wl;
            accR[0][j] += a0 * wr; accR[1][j] += a1 * wr;
        }
    }
    #pragma unroll
    for (int i = 0; i < 2; ++i) {
        int r = row0 + tr * 2 + i;
        if (r < n) {
            #pragma unroll
            for (int j = 0; j < 5; ++j) {
                int c = tc + j;
                g_xl2[(size_t)r * C2 + c] = accL[i][j] + bl[c];
                g_xr2[(size_t)r * C2 + c] = accR[i][j] + br[c];
            }
        }
    }
}

// ---------------------------------------------------------------------------
// K7: layer-2 aggregation + log_softmax. One warp per node.
__global__ void __launch_bounds__(256) k_agg2(
    const float* __restrict__ att2, const float* __restrict__ bias2,
    float* __restrict__ out, int n)
{
    int wid = (blockIdx.x * blockDim.x + threadIdx.x) >> 5;
    int lane = threadIdx.x & 31;
    if (wid >= n) return;
    const bool hasB = lane < 8;
    const int cA = lane, cB = 32 + lane;

    float xrA = g_xr2[(size_t)wid * C2 + cA];
    float xrB = hasB ? g_xr2[(size_t)wid * C2 + cB] : 0.f;
    float aA = att2[cA];
    float aB = hasB ? att2[cB] : 0.f;

    float mx = -1e30f, s = 0.f, accA = 0.f, accB = 0.f;
    int beg = g_rowptr[wid];
    int cnt = g_rowptr[wid + 1] - beg;

    for (int it = -1; it < cnt; ++it) {
        int src = (it < 0) ? wid : g_col[beg + it];
        float lA = g_xl2[(size_t)src * C2 + cA];
        float lB = hasB ? g_xl2[(size_t)src * C2 + cB] : 0.f;
        float mA = lA + xrA, mB = lB + xrB;
        float hA = mA > 0.f ? mA : NEG_SLOPE * mA;
        float hB = mB > 0.f ? mB : NEG_SLOPE * mB;
        float p = hA * aA + hB * aB;
        #pragma unroll
        for (int d = 16; d; d >>= 1) p += __shfl_xor_sync(0xffffffffu, p, d);
        if (p > mx) {
            float f = __expf(mx - p);
            s *= f; accA *= f; accB *= f; mx = p;
        }
        float w = __expf(p - mx);
        s += w;
        accA += w * lA;
        accB += w * lB;
    }
    float oA = accA / s + bias2[cA];
    float oB = hasB ? (accB / s + bias2[cB]) : -1e30f;

    // log_softmax over the 40 values spread across the warp
    float m = fmaxf(oA, oB);
    #pragma unroll
    for (int d = 16; d; d >>= 1) m = fmaxf(m, __shfl_xor_sync(0xffffffffu, m, d));
    float se = __expf(oA - m) + (hasB ? __expf(oB - m) : 0.f);
    #pragma unroll
    for (int d = 16; d; d >>= 1) se += __shfl_xor_sync(0xffffffffu, se, d);
    float lse = m + __logf(se);

    out[(size_t)wid * C2 + cA] = oA - lse;
    if (hasB) out[(size_t)wid * C2 + cB] = oB - lse;
}

// ---------------------------------------------------------------------------
extern "C" void kernel_launch(void* const* d_in, const int* in_sizes, int n_in,
                              void* d_out, int out_size)
{
    const float* x    = (const float*)d_in[0];
    const int*   ei   = (const int*)  d_in[1];
    const float* W_l1 = (const float*)d_in[2];
    const float* b_l1 = (const float*)d_in[3];
    const float* W_r1 = (const float*)d_in[4];
    const float* b_r1 = (const float*)d_in[5];
    const float* att1 = (const float*)d_in[6];
    const float* bias1= (const float*)d_in[7];
    const float* W_l2 = (const float*)d_in[8];
    const float* b_l2 = (const float*)d_in[9];
    const float* W_r2 = (const float*)d_in[10];
    const float* b_r2 = (const float*)d_in[11];
    const float* att2 = (const float*)d_in[12];
    const float* bias2= (const float*)d_in[13];
    float* out = (float*)d_out;

    const int n = in_sizes[0] / IN_DIM;        // 100000
    const int E = in_sizes[1] / 2;             // 1600000
    const int* src = ei;
    const int* dst = ei + E;

    const int NB = (n + 1023) >> 10;           // scan blocks (98)

    // CSR build
    k_zero<<<(n + 255) / 256, 256>>>(n);
    k_hist<<<(E + 255) / 256, 256>>>(dst, E);
    k_scan_block<<<NB, 1024>>>(n);
    k_scan_sums<<<1, 128>>>(NB);
    k_scan_add<<<(n + 255) / 256, 256>>>(n, NB);
    k_scatter<<<(E + 255) / 256, 256>>>(src, dst, E);

    // layer 1
    k_gemm1<<<(n + 127) / 128, 256>>>(x, W_l1, b_l1, W_r1, b_r1, n);
    k_agg1<<<(n + 7) / 8, 256>>>(att1, bias1, n);

    // layer 2 + log_softmax
    k_gemm2<<<(n + 63) / 64, 256>>>(W_l2, b_l2, W_r2, b_r2, n);
    k_agg2<<<(n + 7) / 8, 256>>>(att2, bias2, out, n);
}

// round 15
// speedup vs baseline: 1.2213x; 1.2213x over previous
#include <cuda_runtime.h>
#include <cuda_bf16.h>

// ---------------------------------------------------------------------------
// GATv2 x2 on GB300.  GEMM1 scalar-FFMA (R2 config, measured 494us total);
// FFMA2 variant measured +106us (R9) — no f32x2 issue-rate gain, +50% LDS.
// Desk analysis: scalar GEMM1 is ~at the fp32 FMA roofline (~195us); next
// lever is tcgen05 tf32, gated on a confirming profile.
// Launch order keeps k_gemm1 at my-launch-index 3 (the ncu capture slot).
// ---------------------------------------------------------------------------

#define NMAX 100000
#define EMAX 1700000
#define IN_DIM 256
#define C1 64            // heads*hid layer 1
#define C2 40            // out dim layer 2
#define NEG_SLOPE 0.2f

// scratch (device globals; no allocation allowed)
__device__ float g_xl1[NMAX * C1];
__device__ float g_xr1[NMAX * C1];
__device__ float g_h  [NMAX * C1];
__device__ float g_xl2[NMAX * C2];
__device__ float g_xr2[NMAX * C2];
__device__ int   g_deg[NMAX];
__device__ int   g_cursor[NMAX];
__device__ int   g_rowptr[NMAX + 1];
__device__ int   g_col[EMAX];
__device__ int   g_bsums[256];   // NB = 98 < 128: safe

// ---------------------------------------------------------------------------
// K0: zero deg + cursor
__global__ void k_zero(int n) {
    int i = blockIdx.x * blockDim.x + threadIdx.x;
    if (i < n) { g_deg[i] = 0; g_cursor[i] = 0; }
}

// K1: degree histogram over dst
__global__ void k_hist(const int* __restrict__ dst, int E) {
    int e = blockIdx.x * blockDim.x + threadIdx.x;
    if (e < E) atomicAdd(&g_deg[dst[e]], 1);
}

// K2a: per-block exclusive scan (1024 elems / block)
__global__ void k_scan_block(int n) {
    __shared__ int warpSums[32];
    int t = threadIdx.x;
    int i = blockIdx.x * 1024 + t;
    int v = (i < n) ? g_deg[i] : 0;
    int x = v;
    #pragma unroll
    for (int d = 1; d < 32; d <<= 1) {
        int y = __shfl_up_sync(0xffffffffu, x, d);
        if ((t & 31) >= d) x += y;
    }
    if ((t & 31) == 31) warpSums[t >> 5] = x;
    __syncthreads();
    if (t < 32) {
        int w = warpSums[t];
        #pragma unroll
        for (int d = 1; d < 32; d <<= 1) {
            int y = __shfl_up_sync(0xffffffffu, w, d);
            if (t >= d) w += y;
        }
        warpSums[t] = w;   // inclusive warp sums
    }
    __syncthreads();
    int warpOff = (t >= 32) ? warpSums[(t >> 5) - 1] : 0;
    int inc = x + warpOff;
    if (i < n) g_rowptr[i] = inc - v;       // exclusive within block
    if (t == 1023) g_bsums[blockIdx.x] = inc;
}

// K2b: parallel scan of block sums (nb <= 128), one block of 128 threads
__global__ void k_scan_sums(int nb) {
    __shared__ int ws[4];
    int t = threadIdx.x;                    // 0..127
    int v = (t < nb) ? g_bsums[t] : 0;
    int x = v;
    #pragma unroll
    for (int d = 1; d < 32; d <<= 1) {
        int y = __shfl_up_sync(0xffffffffu, x, d);
        if ((t & 31) >= d) x += y;
    }
    if ((t & 31) == 31) ws[t >> 5] = x;
    __syncthreads();
    int off = 0;
    #pragma unroll
    for (int w = 0; w < 4; ++w) if (w < (t >> 5)) off += ws[w];
    int inc = x + off;
    if (t <= nb) g_bsums[t] = inc - v;      // exclusive; t==nb gets total
}

// K2c: add block offsets; write rowptr[n]
__global__ void k_scan_add(int n, int nb) {
    int i = blockIdx.x * blockDim.x + threadIdx.x;
    if (i < n) g_rowptr[i] += g_bsums[i >> 10];
    if (i == 0) g_rowptr[n] = g_bsums[nb];
}

// K3: scatter src ids into CSR slots
__global__ void k_scatter(const int* __restrict__ src, const int* __restrict__ dst, int E) {
    int e = blockIdx.x * blockDim.x + threadIdx.x;
    if (e < E) {
        int d = dst[e];
        int pos = g_rowptr[d] + atomicAdd(&g_cursor[d], 1);
        g_col[pos] = src[e];
    }
}

// ---------------------------------------------------------------------------
// K4: GEMM1 (scalar FFMA, R2 version). Block 256 threads, tile 128x64, both W.
// Thread: 8x4 outputs per matrix.
__global__ void __launch_bounds__(256) k_gemm1(
    const float* __restrict__ x,
    const float* __restrict__ Wl, const float* __restrict__ bl,
    const float* __restrict__ Wr, const float* __restrict__ br,
    int n)
{
    __shared__ float As[16][128];
    __shared__ float Bls[16][64];
    __shared__ float Brs[16][64];
    const int t = threadIdx.x;
    const int row0 = blockIdx.x * 128;
    const int tr = t >> 4;         // 0..15 -> rows tr*8..+7
    const int tc = t & 15;         // 0..15 -> cols tc*4..+3

    const int m   = t & 127;       // A-load row
    const int half = t >> 7;       // 0/1 -> k-subrange
    const int r_load = row0 + m;
    const bool rok = (r_load < n);

    const int kb = t >> 4;         // B-load row within chunk
    const int cb = (t & 15) * 4;   // B-load col

    float accL[8][4]; float accR[8][4];
    #pragma unroll
    for (int i = 0; i < 8; ++i)
        #pragma unroll
        for (int j = 0; j < 4; ++j) { accL[i][j] = 0.f; accR[i][j] = 0.f; }

    for (int k0 = 0; k0 < IN_DIM; k0 += 16) {
        float4 v0, v1;
        if (rok) {
            const float4* xp = (const float4*)(x + (size_t)r_load * IN_DIM + k0 + half * 8);
            v0 = xp[0]; v1 = xp[1];
        } else {
            v0 = make_float4(0.f,0.f,0.f,0.f); v1 = v0;
        }
        int kk = half * 8;
        As[kk+0][m] = v0.x; As[kk+1][m] = v0.y; As[kk+2][m] = v0.z; As[kk+3][m] = v0.w;
        As[kk+4][m] = v1.x; As[kk+5][m] = v1.y; As[kk+6][m] = v1.z; As[kk+7][m] = v1.w;
        *(float4*)&Bls[kb][cb] = *(const float4*)&Wl[(size_t)(k0 + kb) * C1 + cb];
        *(float4*)&Brs[kb][cb] = *(const float4*)&Wr[(size_t)(k0 + kb) * C1 + cb];
        __syncthreads();

        #pragma unroll
        for (int k = 0; k < 16; ++k) {
            float4 a0 = *(float4*)&As[k][tr * 8];
            float4 a1 = *(float4*)&As[k][tr * 8 + 4];
            float4 blv = *(float4*)&Bls[k][tc * 4];
            float4 brv = *(float4*)&Brs[k][tc * 4];
            float av[8] = {a0.x,a0.y,a0.z,a0.w,a1.x,a1.y,a1.z,a1.w};
            float blj[4] = {blv.x,blv.y,blv.z,blv.w};
            float brj[4] = {brv.x,brv.y,brv.z,brv.w};
            #pragma unroll
            for (int i = 0; i < 8; ++i)
                #pragma unroll
                for (int j = 0; j < 4; ++j) {
                    accL[i][j] += av[i] * blj[j];
                    accR[i][j] += av[i] * brj[j];
                }
        }
        __syncthreads();
    }

    float4 bly = *(const float4*)&bl[tc * 4];
    float4 bry = *(const float4*)&br[tc * 4];
    #pragma unroll
    for (int i = 0; i < 8; ++i) {
        int r = row0 + tr * 8 + i;
        if (r < n) {
            float4 oL = make_float4(accL[i][0]+bly.x, accL[i][1]+bly.y,
                                    accL[i][2]+bly.z, accL[i][3]+bly.w);
            float4 oR = make_float4(accR[i][0]+bry.x, accR[i][1]+bry.y,
                                    accR[i][2]+bry.z, accR[i][3]+bry.w);
            *(float4*)&g_xl1[(size_t)r * C1 + tc * 4] = oL;
            *(float4*)&g_xr1[(size_t)r * C1 + tc * 4] = oR;
        }
    }
}

// ---------------------------------------------------------------------------
// K5: layer-1 aggregation. One warp per node, online segment softmax.
__global__ void __launch_bounds__(256) k_agg1(
    const float* __restrict__ att, const float* __restrict__ bias, int n)
{
    int wid = (blockIdx.x * blockDim.x + threadIdx.x) >> 5;
    int lane = threadIdx.x & 31;
    if (wid >= n) return;
    const int c0 = lane * 2;
    float2 xrv = *(const float2*)(g_xr1 + (size_t)wid * C1 + c0);
    float a0 = att[c0], a1 = att[c0 + 1];

    float mx = -1e30f, s = 0.f, acc0 = 0.f, acc1 = 0.f;
    int beg = g_rowptr[wid];
    int cnt = g_rowptr[wid + 1] - beg;

    for (int it = -1; it < cnt; ++it) {
        int src = (it < 0) ? wid : g_col[beg + it];
        float2 lv = *(const float2*)(g_xl1 + (size_t)src * C1 + c0);
        float m0 = lv.x + xrv.x, m1 = lv.y + xrv.y;
        float h0 = m0 > 0.f ? m0 : NEG_SLOPE * m0;
        float h1 = m1 > 0.f ? m1 : NEG_SLOPE * m1;
        float p = h0 * a0 + h1 * a1;
        p += __shfl_xor_sync(0xffffffffu, p, 1);
        p += __shfl_xor_sync(0xffffffffu, p, 2);   // head logit in all 4 lanes
        if (p > mx) {
            float f = __expf(mx - p);
            s *= f; acc0 *= f; acc1 *= f; mx = p;
        }
        float w = __expf(p - mx);
        s += w;
        acc0 += w * lv.x;
        acc1 += w * lv.y;
    }
    float o0 = acc0 / s + bias[c0];
    float o1 = acc1 / s + bias[c0 + 1];
    o0 = o0 > 0.f ? o0 : (__expf(o0) - 1.f);   // ELU
    o1 = o1 > 0.f ? o1 : (__expf(o1) - 1.f);
    *(float2*)(g_h + (size_t)wid * C1 + c0) = make_float2(o0, o1);
}

// ---------------------------------------------------------------------------
// K6: GEMM2. Block: 256 threads, tile 64 rows x 40 cols, K=64, both W's.
__global__ void __launch_bounds__(256) k_gemm2(
    const float* __restrict__ Wl, const float* __restrict__ bl,
    const float* __restrict__ Wr, const float* __restrict__ br,
    int n)
{
    __shared__ float hs[64][65];
    __shared__ float Bls[64 * C2];
    __shared__ float Brs[64 * C2];
    const int t = threadIdx.x;
    const int row0 = blockIdx.x * 64;

    for (int i = t; i < 64 * C2; i += 256) { Bls[i] = Wl[i]; Brs[i] = Wr[i]; }
    #pragma unroll
    for (int j = 0; j < 16; ++j) {
        int linear = j * 256 + t;
        int m = linear >> 6, k = linear & 63;
        int r = row0 + m;
        hs[m][k] = (r < n) ? g_h[(size_t)r * C1 + k] : 0.f;
    }
    __syncthreads();

    const int tr = t >> 3;          // 0..31 -> rows tr*2, tr*2+1
    const int tc = (t & 7) * 5;     // cols tc..tc+4
    float accL[2][5] = {{0}}; float accR[2][5] = {{0}};

    #pragma unroll 8
    for (int k = 0; k < 64; ++k) {
        float a0 = hs[tr * 2][k];
        float a1 = hs[tr * 2 + 1][k];
        #pragma unroll
        for (int j = 0; j < 5; ++j) {
            float wl = Bls[k * C2 + tc + j];
            float wr = Brs[k * C2 + tc + j];
            accL[0][j] += a0 * wl; accL[1][j] += a1 * wl;
            accR[0][j] += a0 * wr; accR[1][j] += a1 * wr;
        }
    }
    #pragma unroll
    for (int i = 0; i < 2; ++i) {
        int r = row0 + tr * 2 + i;
        if (r < n) {
            #pragma unroll
            for (int j = 0; j < 5; ++j) {
                int c = tc + j;
                g_xl2[(size_t)r * C2 + c] = accL[i][j] + bl[c];
                g_xr2[(size_t)r * C2 + c] = accR[i][j] + br[c];
            }
        }
    }
}

// ---------------------------------------------------------------------------
// K7: layer-2 aggregation + log_softmax. One warp per node.
__global__ void __launch_bounds__(256) k_agg2(
    const float* __restrict__ att2, const float* __restrict__ bias2,
    float* __restrict__ out, int n)
{
    int wid = (blockIdx.x * blockDim.x + threadIdx.x) >> 5;
    int lane = threadIdx.x & 31;
    if (wid >= n) return;
    const bool hasB = lane < 8;
    const int cA = lane, cB = 32 + lane;

    float xrA = g_xr2[(size_t)wid * C2 + cA];
    float xrB = hasB ? g_xr2[(size_t)wid * C2 + cB] : 0.f;
    float aA = att2[cA];
    float aB = hasB ? att2[cB] : 0.f;

    float mx = -1e30f, s = 0.f, accA = 0.f, accB = 0.f;
    int beg = g_rowptr[wid];
    int cnt = g_rowptr[wid + 1] - beg;

    for (int it = -1; it < cnt; ++it) {
        int src = (it < 0) ? wid : g_col[beg + it];
        float lA = g_xl2[(size_t)src * C2 + cA];
        float lB = hasB ? g_xl2[(size_t)src * C2 + cB] : 0.f;
        float mA = lA + xrA, mB = lB + xrB;
        float hA = mA > 0.f ? mA : NEG_SLOPE * mA;
        float hB = mB > 0.f ? mB : NEG_SLOPE * mB;
        float p = hA * aA + hB * aB;
        #pragma unroll
        for (int d = 16; d; d >>= 1) p += __shfl_xor_sync(0xffffffffu, p, d);
        if (p > mx) {
            float f = __expf(mx - p);
            s *= f; accA *= f; accB *= f; mx = p;
        }
        float w = __expf(p - mx);
        s += w;
        accA += w * lA;
        accB += w * lB;
    }
    float oA = accA / s + bias2[cA];
    float oB = hasB ? (accB / s + bias2[cB]) : -1e30f;

    // log_softmax over the 40 values spread across the warp
    float m = fmaxf(oA, oB);
    #pragma unroll
    for (int d = 16; d; d >>= 1) m = fmaxf(m, __shfl_xor_sync(0xffffffffu, m, d));
    float se = __expf(oA - m) + (hasB ? __expf(oB - m) : 0.f);
    #pragma unroll
    for (int d = 16; d; d >>= 1) se += __shfl_xor_sync(0xffffffffu, se, d);
    float lse = m + __logf(se);

    out[(size_t)wid * C2 + cA] = oA - lse;
    if (hasB) out[(size_t)wid * C2 + cB] = oB - lse;
}

// ---------------------------------------------------------------------------
extern "C" void kernel_launch(void* const* d_in, const int* in_sizes, int n_in,
                              void* d_out, int out_size)
{
    const float* x    = (const float*)d_in[0];
    const int*   ei   = (const int*)  d_in[1];
    const float* W_l1 = (const float*)d_in[2];
    const float* b_l1 = (const float*)d_in[3];
    const float* W_r1 = (const float*)d_in[4];
    const float* b_r1 = (const float*)d_in[5];
    const float* att1 = (const float*)d_in[6];
    const float* bias1= (const float*)d_in[7];
    const float* W_l2 = (const float*)d_in[8];
    const float* b_l2 = (const float*)d_in[9];
    const float* W_r2 = (const float*)d_in[10];
    const float* b_r2 = (const float*)d_in[11];
    const float* att2 = (const float*)d_in[12];
    const float* bias2= (const float*)d_in[13];
    float* out = (float*)d_out;

    const int n = in_sizes[0] / IN_DIM;        // 100000
    const int E = in_sizes[1] / 2;             // 1600000
    const int* src = ei;
    const int* dst = ei + E;

    const int NB = (n + 1023) >> 10;           // scan blocks (98)

    // Launch order: k_gemm1 placed at my-launch-index 3 (the ncu capture slot
    // observed in R2/R9). gemm1 is independent of the CSR build, so this is
    // pure reordering on one stream — same total work.
    k_zero<<<(n + 255) / 256, 256>>>(n);                       // 0
    k_hist<<<(E + 255) / 256, 256>>>(dst, E);                  // 1
    k_scan_block<<<NB, 1024>>>(n);                             // 2
    k_gemm1<<<(n + 127) / 128, 256>>>(x, W_l1, b_l1, W_r1, b_r1, n);  // 3 <- profiled
    k_scan_sums<<<1, 128>>>(NB);                               // 4
    k_scan_add<<<(n + 255) / 256, 256>>>(n, NB);               // 5
    k_scatter<<<(E + 255) / 256, 256>>>(src, dst, E);          // 6
    k_agg1<<<(n + 7) / 8, 256>>>(att1, bias1, n);              // 7
    k_gemm2<<<(n + 63) / 64, 256>>>(W_l2, b_l2, W_r2, b_r2, n);// 8
    k_agg2<<<(n + 7) / 8, 256>>>(att2, bias2, out, n);         // 9
}